// round 9
// baseline (speedup 1.0000x reference)
#include <cuda_runtime.h>

// Problem constants
#define BB   64
#define NN   883
#define NPAD 912    // NN padded to multiple of TM (19*48)
#define EE   10
#define CINx 66     // DIN + DOUT
#define DO   64     // DOUT
#define OG   128    // gate output width (2*DOUT)
#define OU   64     // update output width

// L@x tiling
#define TN   128
#define TM   48
#define CP   72     // padded channels
#define LXT  288    // 32 rg x 9 cg

typedef unsigned long long ull;

// ---------------- scratch (device globals; no allocation allowed) ----------------
__device__ __align__(16) float g_Wg[NN * 2 * CINx * OG];   // per-node gate weights
__device__ __align__(16) float g_bg[NN * OG];
__device__ __align__(16) float g_Wu[NN * 2 * CINx * OU];   // per-node update weights
__device__ __align__(16) float g_bu[NN * OU];
__device__ float g_xs[BB * NN * CINx];       // current DGCN input (concat)
__device__ __align__(16) float g_nv[BB * NPAD * EE];    // nodevec (padded, zero tail)
__device__ float g_d[BB * NN];               // degree^-0.5
__device__ __align__(16) float g_dxs[BB * NPAD * CP];   // d[m]*xs (padded, zero tail)
__device__ float g_y2[BB * NN * CINx];       // L @ xs
__device__ float g_zr[BB * NN * OG];         // sigmoid(gate out): z | r

__device__ __forceinline__ float sigm(float v) { return 1.f / (1.f + expf(-v)); }

__device__ __forceinline__ ull pk2(float a, float b) {
    ull r; asm("mov.b64 %0, {%1, %2};" : "=l"(r) : "f"(a), "f"(b)); return r;
}
__device__ __forceinline__ ull fma2(ull a, ull b, ull c) {
    ull d; asm("fma.rn.f32x2 %0, %1, %2, %3;" : "=l"(d) : "l"(a), "l"(b), "l"(c)); return d;
}
__device__ __forceinline__ float2 upk(ull v) {
    float2 f; asm("mov.b64 {%0, %1}, %2;" : "=f"(f.x), "=f"(f.y) : "l"(v)); return f;
}

// ---------------- per-node weight pools (float4 vectorized) ----------------
__global__ void k_genw4(const float* __restrict__ emb, const float* __restrict__ pool,
                        float* __restrict__ outw, int J4) {
    int n = blockIdx.y;
    int j = blockIdx.x * blockDim.x + threadIdx.x;
    if (j >= J4) return;
    const float4* p4 = (const float4*)pool;
    float4 acc = make_float4(0.f, 0.f, 0.f, 0.f);
#pragma unroll
    for (int e = 0; e < EE; e++) {
        float w = emb[n * EE + e];
        float4 p = p4[e * J4 + j];
        acc.x += w * p.x; acc.y += w * p.y; acc.z += w * p.z; acc.w += w * p.w;
    }
    ((float4*)outw)[n * J4 + j] = acc;
}

// ---------------- build xs, hyper-net filter, nodevec (padded rows zeroed) --------
__global__ void k_prep(const float* __restrict__ x, const float* __restrict__ state,
                       const float* __restrict__ emb, const float* __restrict__ tim,
                       const float* __restrict__ day, const float* __restrict__ spd,
                       const float* __restrict__ occ,
                       const float* __restrict__ w1, const float* __restrict__ b1,
                       const float* __restrict__ w2, const float* __restrict__ b2,
                       const float* __restrict__ w3, const float* __restrict__ b3,
                       int is_update) {
    int idx = blockIdx.x * blockDim.x + threadIdx.x;   // over BB*NPAD
    if (idx >= BB * NPAD) return;
    int n = idx % NPAD;
    int b = idx / NPAD;
    float* nvp = g_nv + idx * EE;
    if (n >= NN) {                    // zero padded tail rows
#pragma unroll
        for (int e = 0; e < EE; e++) nvp[e] = 0.f;
        return;
    }
    int bn = b * NN + n;

    float c[CINx];
    c[0] = x[bn * 2 + 0];
    c[1] = x[bn * 2 + 1];
    const float* st = state + bn * DO;
    if (is_update) {
        const float* z = g_zr + bn * OG;   // z = zr[..., :64]
#pragma unroll
        for (int j = 0; j < DO; j++) c[2 + j] = z[j] * st[j];
    } else {
#pragma unroll
        for (int j = 0; j < DO; j++) c[2 + j] = st[j];
    }
    float* xo = g_xs + bn * CINx;
#pragma unroll
    for (int i = 0; i < CINx; i++) xo[i] = c[i];

    // fc1 (66->16) sigmoid
    float h1[16];
#pragma unroll
    for (int t = 0; t < 16; t++) h1[t] = b1[t];
    for (int i = 0; i < CINx; i++) {
        float ci = c[i];
#pragma unroll
        for (int t = 0; t < 16; t++) h1[t] += ci * w1[i * 16 + t];
    }
#pragma unroll
    for (int t = 0; t < 16; t++) h1[t] = sigm(h1[t]);

    // fc2 (16->2) sigmoid
    float h2[2];
#pragma unroll
    for (int u = 0; u < 2; u++) {
        float s = b2[u];
#pragma unroll
        for (int t = 0; t < 16; t++) s += h1[t] * w2[t * 2 + u];
        h2[u] = sigm(s);
    }

    // fc3 (2->10); dyn modulated embedding; nodevec = tanh
#pragma unroll
    for (int e = 0; e < EE; e++) {
        float f = b3[e] + h2[0] * w3[e] + h2[1] * w3[EE + e];
        float dyn = emb[n * EE + e] * tim[bn * EE + e] * day[bn * EE + e]
                  * spd[bn * EE + e] * occ[bn * EE + e];
        nvp[e] = tanhf(dyn * f);
    }
}

// ---------------- d[b,n] = rsqrt( sum_m relu(nv_n . nv_m) ); fused dxs write -------
// Thread n also writes its own padded, scaled dxs row (tail channels + rows zeroed).
__global__ void k_degree() {
    __shared__ __align__(16) float s_nv[NN * EE];   // 35.3 KB
    int b = blockIdx.y;
    const float* nvb = g_nv + b * NPAD * EE;
    for (int i = threadIdx.x; i < NN * EE; i += blockDim.x) s_nv[i] = nvb[i];
    __syncthreads();
    int n = blockIdx.x * blockDim.x + threadIdx.x;
    if (n >= NPAD) return;
    float4* dxr = (float4*)(g_dxs + (b * NPAD + n) * CP);
    if (n >= NN) {                       // zero tail rows
#pragma unroll
        for (int t = 0; t < CP / 4; t++) dxr[t] = make_float4(0.f, 0.f, 0.f, 0.f);
        return;
    }
    ull my[5];
    const ull* myp = (const ull*)(s_nv + n * EE);
#pragma unroll
    for (int e = 0; e < 5; e++) my[e] = myp[e];
    float sum = 0.f;
#pragma unroll 2
    for (int m = 0; m < NN; m++) {
        const ull* row = (const ull*)(s_nv + m * EE);
        ull d2 = 0ull;
#pragma unroll
        for (int e = 0; e < 5; e++) d2 = fma2(my[e], row[e], d2);
        float2 f = upk(d2);
        sum += fmaxf(f.x + f.y, 0.f);
    }
    float dn = rsqrtf(sum);
    g_d[b * NN + n] = dn;
    // fused scale: dxs row = dn * xs row, channels 66..71 zero
    const float* xr = g_xs + (b * NN + n) * CINx;
#pragma unroll
    for (int t = 0; t < 16; t++) {
        float4 v;
        v.x = dn * xr[t * 4 + 0]; v.y = dn * xr[t * 4 + 1];
        v.z = dn * xr[t * 4 + 2]; v.w = dn * xr[t * 4 + 3];
        dxr[t] = v;
    }
    dxr[16] = make_float4(dn * xr[64], dn * xr[65], 0.f, 0.f);
    dxr[17] = make_float4(0.f, 0.f, 0.f, 0.f);
}

// ---------------- y2 = xs - d_n * (relu(NV NV^T) @ (d*xs)) -------------------------
// 288 threads. Phase 1: threads<256, row (tid&127), mm half per tid>>7.
// Phase 2: all 288 = (rg 0..31: 4 rows) x (cg 0..8: 8 channels), ch-pair FFMA2.
__global__ void __launch_bounds__(LXT, 3) k_lx() {
    __shared__ __align__(16) float s_nvm[TM * EE];     // 1.9 KB
    __shared__ __align__(16) float s_dx[TM * CP];      // 13.5 KB
    __shared__ __align__(16) float s_a[TM * TN];       // 24 KB

    int b = blockIdx.y;
    int n0 = blockIdx.x * TN;
    int tid = threadIdx.x;
    const float* nvb = g_nv + b * NPAD * EE;

    // phase-1 row nodevec in registers (packed); max row 895 < NPAD
    ull nvr[5];
    {
        int n = n0 + (tid & 127);
        const ull* p = (const ull*)(nvb + n * EE);
#pragma unroll
        for (int e = 0; e < 5; e++) nvr[e] = p[e];
    }
    bool p1 = tid < 256;
    int prow = tid & 127;
    int mlo = (tid >> 7) * (TM / 2);     // 0 or 24

    int rg = tid / 9;     // 0..31 (4 rows each)
    int cg = tid % 9;     // 0..8  (8 channels each)

    // acc[q][t]: row rg*4+q, channel pair (cg*8+2t, cg*8+2t+1)
    ull acc[4][4];
#pragma unroll
    for (int q = 0; q < 4; q++)
#pragma unroll
        for (int t = 0; t < 4; t++) acc[q][t] = 0ull;

    for (int mt = 0; mt < NPAD; mt += TM) {
        __syncthreads();   // protect smem reuse
        {
            const float4* gn = (const float4*)(nvb + mt * EE);
            float4* sn = (float4*)s_nvm;
            for (int i = tid; i < TM * EE / 4; i += LXT) sn[i] = gn[i];
            const float4* gd = (const float4*)(g_dxs + (b * NPAD + mt) * CP);
            float4* sd = (float4*)s_dx;
#pragma unroll
            for (int i = tid; i < TM * CP / 4; i += LXT) sd[i] = gd[i];
        }
        __syncthreads();

        // phase 1: A[mm][prow] over this thread's mm half
        if (p1) {
#pragma unroll 2
            for (int mm = mlo; mm < mlo + TM / 2; mm++) {
                const ull* q = (const ull*)(s_nvm + mm * EE);
                ull d2 = 0ull;
#pragma unroll
                for (int e = 0; e < 5; e++) d2 = fma2(nvr[e], q[e], d2);
                float2 f = upk(d2);
                s_a[mm * TN + prow] = fmaxf(f.x + f.y, 0.f);
            }
        }
        __syncthreads();

        // phase 2: 4 rows x 8 channels per thread
#pragma unroll 1
        for (int mm = 0; mm < TM; mm++) {
            float4 a = *(const float4*)(s_a + mm * TN + rg * 4);
            const ulonglong2* vp = (const ulonglong2*)(s_dx + mm * CP + cg * 8);
            ulonglong2 v0 = vp[0];
            ulonglong2 v1 = vp[1];
            ull pa0 = pk2(a.x, a.x), pa1 = pk2(a.y, a.y);
            ull pa2 = pk2(a.z, a.z), pa3 = pk2(a.w, a.w);
            acc[0][0] = fma2(pa0, v0.x, acc[0][0]);
            acc[0][1] = fma2(pa0, v0.y, acc[0][1]);
            acc[0][2] = fma2(pa0, v1.x, acc[0][2]);
            acc[0][3] = fma2(pa0, v1.y, acc[0][3]);
            acc[1][0] = fma2(pa1, v0.x, acc[1][0]);
            acc[1][1] = fma2(pa1, v0.y, acc[1][1]);
            acc[1][2] = fma2(pa1, v1.x, acc[1][2]);
            acc[1][3] = fma2(pa1, v1.y, acc[1][3]);
            acc[2][0] = fma2(pa2, v0.x, acc[2][0]);
            acc[2][1] = fma2(pa2, v0.y, acc[2][1]);
            acc[2][2] = fma2(pa2, v1.x, acc[2][2]);
            acc[2][3] = fma2(pa2, v1.y, acc[2][3]);
            acc[3][0] = fma2(pa3, v0.x, acc[3][0]);
            acc[3][1] = fma2(pa3, v0.y, acc[3][1]);
            acc[3][2] = fma2(pa3, v1.x, acc[3][2]);
            acc[3][3] = fma2(pa3, v1.y, acc[3][3]);
        }
    }

#pragma unroll
    for (int q = 0; q < 4; q++) {
        int n = n0 + rg * 4 + q;
        if (n >= NN) continue;
        float dn = g_d[b * NN + n];
        int base = (b * NN + n) * CINx;
        int c0 = cg * 8;
#pragma unroll
        for (int t = 0; t < 4; t++) {
            float2 f = upk(acc[q][t]);
            int c = c0 + 2 * t;
            if (c < CINx)     g_y2[base + c]     = g_xs[base + c]     - dn * f.x;
            if (c + 1 < CINx) g_y2[base + c + 1] = g_xs[base + c + 1] - dn * f.y;
        }
    }
}

// ---------------- out[b,n,o] = sum_ki xg[b,n,k,i] W[n,k,i,o] + bias ----------------
__global__ void k_out(const float* __restrict__ W, const float* __restrict__ bias,
                      const float* __restrict__ state, int Ot, int mode,
                      float* __restrict__ outp) {
    __shared__ __align__(16) float sW[2 * CINx * 64];   // W[n,:,:, og*64..+63]
    __shared__ __align__(16) float sf[132 * 16];        // 16 batches, swizzled

    int n  = blockIdx.y;
    int og = blockIdx.x;
    int tid = threadIdx.x;
    int ol  = tid & 63;     // local o
    int grp = tid >> 6;     // 0/1

    {
        const float4* W4 = (const float4*)(W + n * 132 * Ot + og * 64);
        int ot4 = Ot >> 2;
        float4* sW4 = (float4*)sW;
        for (int idx = tid; idx < 132 * 16; idx += 128) {
            int iki = idx >> 4, o4 = idx & 15;
            sW4[iki * 16 + o4] = W4[iki * ot4 + o4];
        }
    }
    float bval = bias[n * Ot + og * 64 + ol];

    for (int bt = 0; bt < 4; bt++) {      // 4 chunks of 16 batches
        __syncthreads();
        for (int idx = tid; idx < 16 * 132; idx += 128) {
            int bb = idx / 132, ii = idx % 132;
            int base = ((bt * 16 + bb) * NN + n) * CINx;
            float v = (ii < CINx) ? g_xs[base + ii] : g_y2[base + ii - CINx];
            int w = ii * 16 + ((((bb >> 2) ^ (ii & 3)) << 2) | (bb & 3));
            sf[w] = v;
        }
        __syncthreads();

        ull acc[4];
#pragma unroll
        for (int k = 0; k < 4; k++) acc[k] = pk2(bval, bval);

        for (int ii = 0; ii < 132; ii++) {
            float w = sW[ii * 64 + ol];
            ull wp = pk2(w, w);
            const ulonglong2* p = (const ulonglong2*)(sf + ii * 16);
            ulonglong2 v0 = p[(2 * grp) ^ (ii & 3)];
            ulonglong2 v1 = p[(2 * grp + 1) ^ (ii & 3)];
            acc[0] = fma2(wp, v0.x, acc[0]);
            acc[1] = fma2(wp, v0.y, acc[1]);
            acc[2] = fma2(wp, v1.x, acc[2]);
            acc[3] = fma2(wp, v1.y, acc[3]);
        }

#pragma unroll
        for (int k = 0; k < 4; k++) {
            float2 f = upk(acc[k]);
            float vv[2] = {f.x, f.y};
#pragma unroll
            for (int h = 0; h < 2; h++) {
                int b = bt * 16 + grp * 8 + k * 2 + h;
                if (mode == 0) {
                    g_zr[(b * NN + n) * OG + og * 64 + ol] = sigm(vv[h]);
                } else {
                    float hc = tanhf(vv[h]);
                    float r  = g_zr[(b * NN + n) * OG + 64 + ol];
                    float st = state[(b * NN + n) * DO + ol];
                    outp[(b * NN + n) * DO + ol] = r * st + (1.f - r) * hc;
                }
            }
        }
    }
}

// ---------------- launch (gate k_lx at stream position 4 for the ncu window) -------
extern "C" void kernel_launch(void* const* d_in, const int* in_sizes, int n_in,
                              void* d_out, int out_size) {
    const float* x     = (const float*)d_in[0];
    const float* state = (const float*)d_in[1];
    const float* emb   = (const float*)d_in[2];
    const float* tim   = (const float*)d_in[3];
    const float* day   = (const float*)d_in[4];
    const float* spd   = (const float*)d_in[5];
    const float* occ   = (const float*)d_in[6];
    const float* gwp   = (const float*)d_in[7];
    const float* gbp   = (const float*)d_in[8];
    const float* g1w = (const float*)d_in[9],  *g1b = (const float*)d_in[10];
    const float* g2w = (const float*)d_in[11], *g2b = (const float*)d_in[12];
    const float* g3w = (const float*)d_in[13], *g3b = (const float*)d_in[14];
    const float* uwp = (const float*)d_in[15], *ubp = (const float*)d_in[16];
    const float* u1w = (const float*)d_in[17], *u1b = (const float*)d_in[18];
    const float* u2w = (const float*)d_in[19], *u2b = (const float*)d_in[20];
    const float* u3w = (const float*)d_in[21], *u3b = (const float*)d_in[22];
    float* out = (float*)d_out;

    float *pWg, *pbg, *pWu, *pbu;
    cudaGetSymbolAddress((void**)&pWg, g_Wg);
    cudaGetSymbolAddress((void**)&pbg, g_bg);
    cudaGetSymbolAddress((void**)&pWu, g_Wu);
    cudaGetSymbolAddress((void**)&pbu, g_bu);

    int npr = BB * NPAD;

    // --- gate DGCN ---
    k_prep<<<(npr + 127) / 128, 128>>>(x, state, emb, tim, day, spd, occ,          // 1
                                       g1w, g1b, g2w, g2b, g3w, g3b, 0);
    k_degree<<<dim3(2, BB), 512>>>();                                              // 2
    k_genw4<<<dim3((2 * CINx * OG / 4 + 127) / 128, NN), 128>>>(emb, gwp, pWg,     // 3
                                                                2 * CINx * OG / 4);
    k_lx<<<dim3((NN + TN - 1) / TN, BB), LXT>>>();                                 // 4 <- ncu
    k_genw4<<<dim3(1, NN), 128>>>(emb, gbp, pbg, OG / 4);                          // 5
    k_out<<<dim3(2, NN), 128>>>(pWg, pbg, state, OG, 0, nullptr);                  // 6

    // --- update DGCN (cand input = [x, z*state]) + GRU epilogue ---
    k_prep<<<(npr + 127) / 128, 128>>>(x, state, emb, tim, day, spd, occ,          // 7
                                       u1w, u1b, u2w, u2b, u3w, u3b, 1);
    k_degree<<<dim3(2, BB), 512>>>();                                              // 8
    k_lx<<<dim3((NN + TN - 1) / TN, BB), LXT>>>();                                 // 9
    k_genw4<<<dim3((2 * CINx * OU / 4 + 127) / 128, NN), 128>>>(emb, uwp, pWu,     // 10
                                                                2 * CINx * OU / 4);
    k_genw4<<<dim3(1, NN), 128>>>(emb, ubp, pbu, OU / 4);                          // 11
    k_out<<<dim3(1, NN), 128>>>(pWu, pbu, state, OU, 1, out);                      // 12
}

// round 12
// speedup vs baseline: 1.1496x; 1.1496x over previous
#include <cuda_runtime.h>

// Problem constants
#define BB   64
#define NN   883
#define NPAD 912    // NN padded to multiple of TM (19*48)
#define EE   10
#define CINx 66     // DIN + DOUT
#define DO   64     // DOUT
#define OG   128    // gate output width (2*DOUT)
#define OU   64     // update output width

// L@x tiling (R7 config + slot-remapped v rows)
#define TN   128
#define TM   48
#define DXQ  20     // float4 slots per dxs row (80 floats)
#define LXT  160    // threads: phase1 uses 128, phase2 uses 144

typedef unsigned long long ull;

// ---------------- scratch (device globals; no allocation allowed) ----------------
__device__ __align__(16) float g_Wg[NN * 2 * CINx * OG];   // per-node gate weights
__device__ __align__(16) float g_bg[NN * OG];
__device__ __align__(16) float g_Wu[NN * 2 * CINx * OU];   // per-node update weights
__device__ __align__(16) float g_bu[NN * OU];
__device__ float g_xs[BB * NN * CINx];       // current DGCN input (concat)
__device__ __align__(16) float g_nv[BB * NPAD * EE];    // nodevec (padded, zero tail)
__device__ float g_d[BB * NN];               // degree^-0.5
__device__ __align__(16) float g_dxs[BB * NPAD * DXQ * 4]; // slot-mapped d*xs (18.7MB)
__device__ float g_y2[BB * NN * CINx];       // L @ xs
__device__ float g_zr[BB * NN * OG];         // sigmoid(gate out): z | r

__device__ __forceinline__ float sigm(float v) { return 1.f / (1.f + expf(-v)); }

__device__ __forceinline__ ull pk2(float a, float b) {
    ull r; asm("mov.b64 %0, {%1, %2};" : "=l"(r) : "f"(a), "f"(b)); return r;
}
__device__ __forceinline__ ull fma2(ull a, ull b, ull c) {
    ull d; asm("fma.rn.f32x2 %0, %1, %2, %3;" : "=l"(d) : "l"(a), "l"(b), "l"(c)); return d;
}
__device__ __forceinline__ float2 upk(ull v) {
    float2 f; asm("mov.b64 {%0, %1}, %2;" : "=f"(f.x), "=f"(f.y) : "l"(v)); return f;
}

// ---------------- per-node weight pools (float4 vectorized) ----------------
__global__ void k_genw4(const float* __restrict__ emb, const float* __restrict__ pool,
                        float* __restrict__ outw, int J4) {
    int n = blockIdx.y;
    int j = blockIdx.x * blockDim.x + threadIdx.x;
    if (j >= J4) return;
    const float4* p4 = (const float4*)pool;
    float4 acc = make_float4(0.f, 0.f, 0.f, 0.f);
#pragma unroll
    for (int e = 0; e < EE; e++) {
        float w = emb[n * EE + e];
        float4 p = p4[e * J4 + j];
        acc.x += w * p.x; acc.y += w * p.y; acc.z += w * p.z; acc.w += w * p.w;
    }
    ((float4*)outw)[n * J4 + j] = acc;
}

// ---------------- build xs, hyper-net filter, nodevec (padded rows zeroed) --------
__global__ void k_prep(const float* __restrict__ x, const float* __restrict__ state,
                       const float* __restrict__ emb, const float* __restrict__ tim,
                       const float* __restrict__ day, const float* __restrict__ spd,
                       const float* __restrict__ occ,
                       const float* __restrict__ w1, const float* __restrict__ b1,
                       const float* __restrict__ w2, const float* __restrict__ b2,
                       const float* __restrict__ w3, const float* __restrict__ b3,
                       int is_update) {
    int idx = blockIdx.x * blockDim.x + threadIdx.x;   // over BB*NPAD
    if (idx >= BB * NPAD) return;
    int n = idx % NPAD;
    int b = idx / NPAD;
    float* nvp = g_nv + idx * EE;
    if (n >= NN) {                    // zero padded tail rows
#pragma unroll
        for (int e = 0; e < EE; e++) nvp[e] = 0.f;
        return;
    }
    int bn = b * NN + n;

    float c[CINx];
    c[0] = x[bn * 2 + 0];
    c[1] = x[bn * 2 + 1];
    const float* st = state + bn * DO;
    if (is_update) {
        const float* z = g_zr + bn * OG;   // z = zr[..., :64]
#pragma unroll
        for (int j = 0; j < DO; j++) c[2 + j] = z[j] * st[j];
    } else {
#pragma unroll
        for (int j = 0; j < DO; j++) c[2 + j] = st[j];
    }
    float* xo = g_xs + bn * CINx;
#pragma unroll
    for (int i = 0; i < CINx; i++) xo[i] = c[i];

    // fc1 (66->16) sigmoid
    float h1[16];
#pragma unroll
    for (int t = 0; t < 16; t++) h1[t] = b1[t];
    for (int i = 0; i < CINx; i++) {
        float ci = c[i];
#pragma unroll
        for (int t = 0; t < 16; t++) h1[t] += ci * w1[i * 16 + t];
    }
#pragma unroll
    for (int t = 0; t < 16; t++) h1[t] = sigm(h1[t]);

    // fc2 (16->2) sigmoid
    float h2[2];
#pragma unroll
    for (int u = 0; u < 2; u++) {
        float s = b2[u];
#pragma unroll
        for (int t = 0; t < 16; t++) s += h1[t] * w2[t * 2 + u];
        h2[u] = sigm(s);
    }

    // fc3 (2->10); dyn modulated embedding; nodevec = tanh
#pragma unroll
    for (int e = 0; e < EE; e++) {
        float f = b3[e] + h2[0] * w3[e] + h2[1] * w3[EE + e];
        float dyn = emb[n * EE + e] * tim[bn * EE + e] * day[bn * EE + e]
                  * spd[bn * EE + e] * occ[bn * EE + e];
        nvp[e] = tanhf(dyn * f);
    }
}

// ---------------- d[b,n] = rsqrt( sum_m relu(nv_n . nv_m) ); fused slot-dxs write --
// Slot map: channel-quad j (j=0..15) -> slot j; quad16 (ch 64-67, ch66/67=0) ->
// slot 17; slots 16, 18, 19 zero. Tail rows fully zero.
__global__ void k_degree() {
    __shared__ __align__(16) float s_nv[NN * EE];   // 35.3 KB
    int b = blockIdx.y;
    const float* nvb = g_nv + b * NPAD * EE;
    for (int i = threadIdx.x; i < NN * EE; i += blockDim.x) s_nv[i] = nvb[i];
    __syncthreads();
    int n = blockIdx.x * blockDim.x + threadIdx.x;
    if (n >= NPAD) return;
    float4* dxr = (float4*)(g_dxs + (b * NPAD + n) * (DXQ * 4));
    float4 z4 = make_float4(0.f, 0.f, 0.f, 0.f);
    if (n >= NN) {                       // zero tail rows
#pragma unroll
        for (int t = 0; t < DXQ; t++) dxr[t] = z4;
        return;
    }
    ull my[5];
    const ull* myp = (const ull*)(s_nv + n * EE);
#pragma unroll
    for (int e = 0; e < 5; e++) my[e] = myp[e];
    float sum = 0.f;
#pragma unroll 2
    for (int m = 0; m < NN; m++) {
        const ull* row = (const ull*)(s_nv + m * EE);
        ull d2 = 0ull;
#pragma unroll
        for (int e = 0; e < 5; e++) d2 = fma2(my[e], row[e], d2);
        float2 f = upk(d2);
        sum += fmaxf(f.x + f.y, 0.f);
    }
    float dn = rsqrtf(sum);
    g_d[b * NN + n] = dn;
    // fused scale into slot layout
    const float* xr = g_xs + (b * NN + n) * CINx;
#pragma unroll
    for (int j = 0; j < 16; j++) {
        float4 v;
        v.x = dn * xr[j * 4 + 0]; v.y = dn * xr[j * 4 + 1];
        v.z = dn * xr[j * 4 + 2]; v.w = dn * xr[j * 4 + 3];
        dxr[j] = v;
    }
    dxr[16] = z4;
    dxr[17] = make_float4(dn * xr[64], dn * xr[65], 0.f, 0.f);
    dxr[18] = z4;
    dxr[19] = z4;
}

// ---------------- y2 = xs - d_n * (relu(NV NV^T) @ (d*xs)) -------------------------
// Phase 1: thread (tid<128) = one row n, nodevec in regs -> s_a[mm][n].
// Phase 2: thread (tid<144) = 8 rows x 8 channels; v via slot-mapped s_dx
// (v0 slot = 2cg or 17, v1 slot = 2cg+1 or 18) -> max 2-way bank conflicts.
__global__ void __launch_bounds__(LXT, 3) k_lx() {
    __shared__ __align__(16) float s_nvm[TM * EE];       // 1.9 KB
    __shared__ __align__(16) float s_dx[TM * DXQ * 4];   // 15.4 KB
    __shared__ __align__(16) float s_a[TM * TN];         // 24 KB

    int b = blockIdx.y;
    int n0 = blockIdx.x * TN;
    int tid = threadIdx.x;
    const float* nvb = g_nv + b * NPAD * EE;

    // phase-1 row nodevec in registers (packed); max row 895 < NPAD
    ull nvr[5];
    {
        int n = n0 + ((tid < TN) ? tid : 0);
        const ull* p = (const ull*)(nvb + n * EE);
#pragma unroll
        for (int e = 0; e < 5; e++) nvr[e] = p[e];
    }

    int rg = tid / 9;     // 0..15 (8 rows each)
    int cg = tid % 9;     // 0..8  (8 channels each)
    bool p2 = tid < 144;
    // slot offsets (in floats) for this thread's two channel quads
    int v0off = (cg < 8) ? (8 * cg) : 68;          // slot 2cg | slot 17
    int v1off = (cg < 8) ? (8 * cg + 4) : 72;      // slot 2cg+1 | slot 18

    ull acc[8][4];
#pragma unroll
    for (int q = 0; q < 8; q++)
#pragma unroll
        for (int t = 0; t < 4; t++) acc[q][t] = 0ull;

    for (int mt = 0; mt < NPAD; mt += TM) {
        __syncthreads();   // protect smem reuse
        {
            const float4* gn = (const float4*)(nvb + mt * EE);
            float4* sn = (float4*)s_nvm;
            for (int i = tid; i < TM * EE / 4; i += LXT) sn[i] = gn[i];
            const float4* gd = (const float4*)(g_dxs + (b * NPAD + mt) * (DXQ * 4));
            float4* sd = (float4*)s_dx;
#pragma unroll
            for (int i = tid; i < TM * DXQ; i += LXT) sd[i] = gd[i];
        }
        __syncthreads();

        // phase 1: A[mm][tid]
        if (tid < TN) {
#pragma unroll 2
            for (int mm = 0; mm < TM; mm++) {
                const ull* q = (const ull*)(s_nvm + mm * EE);
                ull d2 = 0ull;
#pragma unroll
                for (int e = 0; e < 5; e++) d2 = fma2(nvr[e], q[e], d2);
                float2 f = upk(d2);
                s_a[mm * TN + tid] = fmaxf(f.x + f.y, 0.f);
            }
        }
        __syncthreads();

        // phase 2: 8 rows x 8 channels per thread
        if (p2) {
#pragma unroll 1
            for (int mm = 0; mm < TM; mm++) {
                const float* vb = s_dx + mm * (DXQ * 4);
                ulonglong2 v0 = *(const ulonglong2*)(vb + v0off);
                ulonglong2 v1 = *(const ulonglong2*)(vb + v1off);
                const float* ap = s_a + mm * TN + rg * 8;
                float4 a0 = *(const float4*)(ap);
                float4 a1 = *(const float4*)(ap + 4);
                float ar[8] = {a0.x, a0.y, a0.z, a0.w, a1.x, a1.y, a1.z, a1.w};
#pragma unroll
                for (int q = 0; q < 8; q++) {
                    ull pa = pk2(ar[q], ar[q]);
                    acc[q][0] = fma2(pa, v0.x, acc[q][0]);
                    acc[q][1] = fma2(pa, v0.y, acc[q][1]);
                    acc[q][2] = fma2(pa, v1.x, acc[q][2]);
                    acc[q][3] = fma2(pa, v1.y, acc[q][3]);
                }
            }
        }
    }

    if (p2) {
#pragma unroll
        for (int q = 0; q < 8; q++) {
            int n = n0 + rg * 8 + q;
            if (n >= NN) continue;
            float dn = g_d[b * NN + n];
            int base = (b * NN + n) * CINx;
            float vals[8];
#pragma unroll
            for (int t = 0; t < 4; t++) {
                float2 f = upk(acc[q][t]);
                vals[t * 2] = f.x; vals[t * 2 + 1] = f.y;
            }
            int c0 = cg * 8;
#pragma unroll
            for (int t = 0; t < 8; t++) {
                int c = c0 + t;
                if (c < CINx) g_y2[base + c] = g_xs[base + c] - dn * vals[t];
            }
        }
    }
}

// ---------------- out[b,n,o] = sum_ki xg[b,n,k,i] W[n,k,i,o] + bias ----------------
__global__ void k_out(const float* __restrict__ W, const float* __restrict__ bias,
                      const float* __restrict__ state, int Ot, int mode,
                      float* __restrict__ outp) {
    __shared__ __align__(16) float sW[2 * CINx * 64];   // W[n,:,:, og*64..+63]
    __shared__ __align__(16) float sf[132 * 16];        // 16 batches, swizzled

    int n  = blockIdx.y;
    int og = blockIdx.x;
    int tid = threadIdx.x;
    int ol  = tid & 63;     // local o
    int grp = tid >> 6;     // 0/1

    {
        const float4* W4 = (const float4*)(W + n * 132 * Ot + og * 64);
        int ot4 = Ot >> 2;
        float4* sW4 = (float4*)sW;
        for (int idx = tid; idx < 132 * 16; idx += 128) {
            int iki = idx >> 4, o4 = idx & 15;
            sW4[iki * 16 + o4] = W4[iki * ot4 + o4];
        }
    }
    float bval = bias[n * Ot + og * 64 + ol];

    for (int bt = 0; bt < 4; bt++) {      // 4 chunks of 16 batches
        __syncthreads();
        for (int idx = tid; idx < 16 * 132; idx += 128) {
            int bb = idx / 132, ii = idx % 132;
            int base = ((bt * 16 + bb) * NN + n) * CINx;
            float v = (ii < CINx) ? g_xs[base + ii] : g_y2[base + ii - CINx];
            int w = ii * 16 + ((((bb >> 2) ^ (ii & 3)) << 2) | (bb & 3));
            sf[w] = v;
        }
        __syncthreads();

        ull acc[4];
#pragma unroll
        for (int k = 0; k < 4; k++) acc[k] = pk2(bval, bval);

        for (int ii = 0; ii < 132; ii++) {
            float w = sW[ii * 64 + ol];
            ull wp = pk2(w, w);
            const ulonglong2* p = (const ulonglong2*)(sf + ii * 16);
            ulonglong2 v0 = p[(2 * grp) ^ (ii & 3)];
            ulonglong2 v1 = p[(2 * grp + 1) ^ (ii & 3)];
            acc[0] = fma2(wp, v0.x, acc[0]);
            acc[1] = fma2(wp, v0.y, acc[1]);
            acc[2] = fma2(wp, v1.x, acc[2]);
            acc[3] = fma2(wp, v1.y, acc[3]);
        }

#pragma unroll
        for (int k = 0; k < 4; k++) {
            float2 f = upk(acc[k]);
            float vv[2] = {f.x, f.y};
#pragma unroll
            for (int h = 0; h < 2; h++) {
                int b = bt * 16 + grp * 8 + k * 2 + h;
                if (mode == 0) {
                    g_zr[(b * NN + n) * OG + og * 64 + ol] = sigm(vv[h]);
                } else {
                    float hc = tanhf(vv[h]);
                    float r  = g_zr[(b * NN + n) * OG + 64 + ol];
                    float st = state[(b * NN + n) * DO + ol];
                    outp[(b * NN + n) * DO + ol] = r * st + (1.f - r) * hc;
                }
            }
        }
    }
}

// ---------------- launch (gate k_lx at stream position 4 for the ncu window) -------
extern "C" void kernel_launch(void* const* d_in, const int* in_sizes, int n_in,
                              void* d_out, int out_size) {
    const float* x     = (const float*)d_in[0];
    const float* state = (const float*)d_in[1];
    const float* emb   = (const float*)d_in[2];
    const float* tim   = (const float*)d_in[3];
    const float* day   = (const float*)d_in[4];
    const float* spd   = (const float*)d_in[5];
    const float* occ   = (const float*)d_in[6];
    const float* gwp   = (const float*)d_in[7];
    const float* gbp   = (const float*)d_in[8];
    const float* g1w = (const float*)d_in[9],  *g1b = (const float*)d_in[10];
    const float* g2w = (const float*)d_in[11], *g2b = (const float*)d_in[12];
    const float* g3w = (const float*)d_in[13], *g3b = (const float*)d_in[14];
    const float* uwp = (const float*)d_in[15], *ubp = (const float*)d_in[16];
    const float* u1w = (const float*)d_in[17], *u1b = (const float*)d_in[18];
    const float* u2w = (const float*)d_in[19], *u2b = (const float*)d_in[20];
    const float* u3w = (const float*)d_in[21], *u3b = (const float*)d_in[22];
    float* out = (float*)d_out;

    float *pWg, *pbg, *pWu, *pbu;
    cudaGetSymbolAddress((void**)&pWg, g_Wg);
    cudaGetSymbolAddress((void**)&pbg, g_bg);
    cudaGetSymbolAddress((void**)&pWu, g_Wu);
    cudaGetSymbolAddress((void**)&pbu, g_bu);

    int npr = BB * NPAD;

    // --- gate DGCN ---
    k_prep<<<(npr + 127) / 128, 128>>>(x, state, emb, tim, day, spd, occ,          // 1
                                       g1w, g1b, g2w, g2b, g3w, g3b, 0);
    k_degree<<<dim3(2, BB), 512>>>();                                              // 2
    k_genw4<<<dim3((2 * CINx * OG / 4 + 127) / 128, NN), 128>>>(emb, gwp, pWg,     // 3
                                                                2 * CINx * OG / 4);
    k_lx<<<dim3((NN + TN - 1) / TN, BB), LXT>>>();                                 // 4 <- ncu
    k_genw4<<<dim3(1, NN), 128>>>(emb, gbp, pbg, OG / 4);                          // 5
    k_out<<<dim3(2, NN), 128>>>(pWg, pbg, state, OG, 0, nullptr);                  // 6

    // --- update DGCN (cand input = [x, z*state]) + GRU epilogue ---
    k_prep<<<(npr + 127) / 128, 128>>>(x, state, emb, tim, day, spd, occ,          // 7
                                       u1w, u1b, u2w, u2b, u3w, u3b, 1);
    k_degree<<<dim3(2, BB), 512>>>();                                              // 8
    k_lx<<<dim3((NN + TN - 1) / TN, BB), LXT>>>();                                 // 9
    k_genw4<<<dim3((2 * CINx * OU / 4 + 127) / 128, NN), 128>>>(emb, uwp, pWu,     // 10
                                                                2 * CINx * OU / 4);
    k_genw4<<<dim3(1, NN), 128>>>(emb, ubp, pbu, OU / 4);                          // 11
    k_out<<<dim3(1, NN), 128>>>(pWu, pbu, state, OU, 1, out);                      // 12
}